// round 1
// baseline (speedup 1.0000x reference)
#include <cuda_runtime.h>

#define NN 100000
#define EE 1600000

// ---------------- scratch (static device globals; no allocation) ----------------
__device__ int   g_is64;
__device__ int   g_src[EE];
__device__ int   g_dstE[EE];
__device__ int   g_deg[NN];
__device__ int   g_rowptr[NN + 1];
__device__ int   g_cursor[NN];
__device__ int   g_bsum[128];
__device__ int   g_bexc[128];
__device__ int   g_col[EE + NN];
__device__ float g_h[NN * 64];
__device__ float g_act[NN * 64];
__device__ float g_adst[NN * 8];
__device__ float g_asrc[NN * 8];

// ---------------- dtype detection + edge conversion ----------------
__global__ void k_detect(const void* ei) {
    const long long* p = (const long long*)ei;
    int ok = 1;
    for (int k = 0; k < 8; k++) {
        long long v = p[k];
        if (v < 0 || v >= NN) ok = 0;
    }
    g_is64 = ok;
}

__global__ void k_convert(const void* ei) {
    int e = blockIdx.x * blockDim.x + threadIdx.x;
    if (e >= EE) return;
    if (g_is64) {
        const long long* p = (const long long*)ei;
        g_src[e]  = (int)p[e];
        g_dstE[e] = (int)p[EE + e];
    } else {
        const int* p = (const int*)ei;
        g_src[e]  = p[e];
        g_dstE[e] = p[EE + e];
    }
}

// ---------------- CSR build ----------------
__global__ void k_initdeg() {
    int i = blockIdx.x * blockDim.x + threadIdx.x;
    if (i < NN) g_deg[i] = 1;  // appended self-loop
}

__global__ void k_hist() {
    int e = blockIdx.x * blockDim.x + threadIdx.x;
    if (e >= EE) return;
    int s = g_src[e], d = g_dstE[e];
    if (s != d) atomicAdd(&g_deg[d], 1);  // masked (original self-loop) edges dropped
}

__global__ void k_scan1() {
    __shared__ int sh[1024];
    int tid = threadIdx.x;
    int i = blockIdx.x * 1024 + tid;
    int v = (i < NN) ? g_deg[i] : 0;
    sh[tid] = v;
    __syncthreads();
    for (int o = 1; o < 1024; o <<= 1) {
        int t = (tid >= o) ? sh[tid - o] : 0;
        __syncthreads();
        sh[tid] += t;
        __syncthreads();
    }
    if (i < NN) g_rowptr[i] = sh[tid] - v;  // block-local exclusive
    if (tid == 1023) g_bsum[blockIdx.x] = sh[1023];
}

__global__ void k_scan2(int nb) {
    __shared__ int sh[128];
    int tid = threadIdx.x;
    int v = (tid < nb) ? g_bsum[tid] : 0;
    sh[tid] = v;
    __syncthreads();
    for (int o = 1; o < 128; o <<= 1) {
        int t = (tid >= o) ? sh[tid - o] : 0;
        __syncthreads();
        sh[tid] += t;
        __syncthreads();
    }
    if (tid < nb) g_bexc[tid] = sh[tid] - v;
    if (tid == nb - 1) g_rowptr[NN] = sh[tid];
}

__global__ void k_scan3() {
    int i = blockIdx.x * blockDim.x + threadIdx.x;
    if (i < NN) {
        int r = g_rowptr[i] + g_bexc[i >> 10];
        g_rowptr[i] = r;
        g_cursor[i] = r;
    }
}

__global__ void k_scatter() {
    int e = blockIdx.x * blockDim.x + threadIdx.x;
    if (e >= EE + NN) return;
    if (e < EE) {
        int s = g_src[e], d = g_dstE[e];
        if (s != d) {
            int p = atomicAdd(&g_cursor[d], 1);
            g_col[p] = s;
        }
    } else {
        int n = e - EE;
        int p = atomicAdd(&g_cursor[n], 1);
        g_col[p] = n;
    }
}

// ---------------- tiled FFMA GEMM: C[N,NOUT] = A[N,K] @ W[K,NOUT] ----------------
template <int K, int NOUT, int MROWS, int TX>
__global__ __launch_bounds__(256) void k_gemm(const float* __restrict__ A,
                                              const float* __restrict__ W,
                                              int use_g_act) {
    __shared__ float Ws[K * NOUT];
    __shared__ float As[MROWS][36];
    const float* Ap = use_g_act ? (const float*)g_act : A;

    int tid = threadIdx.x;
    int row0 = blockIdx.x * MROWS;

    for (int i = tid; i < K * NOUT / 4; i += 256)
        ((float4*)Ws)[i] = ((const float4*)W)[i];

    int tx = tid % TX, ty = tid / TX;
    int r0 = ty * 4, c0 = tx * 4;
    float acc[4][4];
#pragma unroll
    for (int i = 0; i < 4; i++)
#pragma unroll
        for (int j = 0; j < 4; j++) acc[i][j] = 0.f;

    for (int kb = 0; kb < K; kb += 32) {
        __syncthreads();
        for (int f = tid; f < MROWS * 8; f += 256) {
            int r = f >> 3, c4 = f & 7;
            float4 v = make_float4(0.f, 0.f, 0.f, 0.f);
            if (row0 + r < NN)
                v = *(const float4*)&Ap[(row0 + r) * K + kb + c4 * 4];
            *(float4*)&As[r][c4 * 4] = v;
        }
        __syncthreads();
#pragma unroll
        for (int kk = 0; kk < 32; kk++) {
            float a0 = As[r0 + 0][kk];
            float a1 = As[r0 + 1][kk];
            float a2 = As[r0 + 2][kk];
            float a3 = As[r0 + 3][kk];
            float4 b = *(float4*)&Ws[(kb + kk) * NOUT + c0];
            acc[0][0] += a0 * b.x; acc[0][1] += a0 * b.y; acc[0][2] += a0 * b.z; acc[0][3] += a0 * b.w;
            acc[1][0] += a1 * b.x; acc[1][1] += a1 * b.y; acc[1][2] += a1 * b.z; acc[1][3] += a1 * b.w;
            acc[2][0] += a2 * b.x; acc[2][1] += a2 * b.y; acc[2][2] += a2 * b.z; acc[2][3] += a2 * b.w;
            acc[3][0] += a3 * b.x; acc[3][1] += a3 * b.y; acc[3][2] += a3 * b.z; acc[3][3] += a3 * b.w;
        }
    }
#pragma unroll
    for (int i = 0; i < 4; i++) {
        int r = row0 + r0 + i;
        if (r < NN)
            *(float4*)&g_h[r * NOUT + c0] =
                make_float4(acc[i][0], acc[i][1], acc[i][2], acc[i][3]);
    }
}

// ---------------- per-node attention dots ----------------
// H=8, C=8: a_dst[n,h] = sum_c h[n,h,c]*att[h,c], a_src uses att[h,8+c]
__global__ __launch_bounds__(256) void k_att8(const float* __restrict__ att) {
    int t = blockIdx.x * blockDim.x + threadIdx.x;
    int n = t >> 5, lane = t & 31;
    if (n >= NN) return;
    float v0 = g_h[n * 64 + lane];
    float v1 = g_h[n * 64 + 32 + lane];
    int hh = lane >> 3, c = lane & 7;
    float d0 = v0 * att[hh * 16 + c];
    float d1 = v1 * att[(hh + 4) * 16 + c];
    float s0 = v0 * att[hh * 16 + 8 + c];
    float s1 = v1 * att[(hh + 4) * 16 + 8 + c];
    for (int o = 1; o < 8; o <<= 1) {
        d0 += __shfl_xor_sync(0xffffffffu, d0, o);
        d1 += __shfl_xor_sync(0xffffffffu, d1, o);
        s0 += __shfl_xor_sync(0xffffffffu, s0, o);
        s1 += __shfl_xor_sync(0xffffffffu, s1, o);
    }
    if (c == 0) {
        g_adst[n * 8 + hh] = d0;
        g_adst[n * 8 + hh + 4] = d1;
        g_asrc[n * 8 + hh] = s0;
        g_asrc[n * 8 + hh + 4] = s1;
    }
}

// H=1, C=32
__global__ __launch_bounds__(256) void k_att32(const float* __restrict__ att) {
    int t = blockIdx.x * blockDim.x + threadIdx.x;
    int n = t >> 5, lane = t & 31;
    if (n >= NN) return;
    float v = g_h[n * 32 + lane];
    float d = v * att[lane];
    float s = v * att[32 + lane];
    for (int o = 1; o < 32; o <<= 1) {
        d += __shfl_xor_sync(0xffffffffu, d, o);
        s += __shfl_xor_sync(0xffffffffu, s, o);
    }
    if (lane == 0) {
        g_adst[n] = d;
        g_asrc[n] = s;
    }
}

// ---------------- fused softmax-aggregate, one warp per dst node ----------------
// H=8, C=8: out[n,h,c] = sum_j ex_j*h[src_j,h,c] / sum_j ex_j  (+bias, optional ELU)
__global__ __launch_bounds__(256) void k_agg8(const float* __restrict__ bias, int do_elu) {
    int t = blockIdx.x * blockDim.x + threadIdx.x;
    int n = t >> 5, lane = t & 31;
    if (n >= NN) return;
    const unsigned full = 0xffffffffu;
    int start = g_rowptr[n], end = g_rowptr[n + 1];

    float adst = g_adst[n * 8 + (lane & 7)];
    float acc0 = 0.f, acc1 = 0.f, dacc = 0.f;

    for (int base = start; base < end; base += 32) {
        int cnt = min(32, end - base);
        int myc = (lane < cnt) ? g_col[base + lane] : 0;
        for (int j = 0; j < cnt; j++) {
            int s = __shfl_sync(full, myc, j);
            float asv = g_asrc[s * 8 + (lane & 7)];
            float al = adst + asv;
            al = al > 0.f ? al : 0.2f * al;
            float ex = __expf(al);
            float w0 = __shfl_sync(full, ex, lane >> 3);
            float w1 = __shfl_sync(full, ex, (lane >> 3) + 4);
            float h0 = g_h[s * 64 + lane];
            float h1 = g_h[s * 64 + 32 + lane];
            acc0 += h0 * w0;
            acc1 += h1 * w1;
            if (lane < 8) dacc += ex;
        }
    }
    float d0 = __shfl_sync(full, dacc, lane >> 3);
    float d1 = __shfl_sync(full, dacc, (lane >> 3) + 4);
    float o0 = acc0 / d0 + bias[lane];
    float o1 = acc1 / d1 + bias[lane + 32];
    if (do_elu) {
        o0 = o0 > 0.f ? o0 : expm1f(o0);
        o1 = o1 > 0.f ? o1 : expm1f(o1);
    }
    g_act[n * 64 + lane] = o0;
    g_act[n * 64 + 32 + lane] = o1;
}

// H=1, C=32, writes final output
__global__ __launch_bounds__(256) void k_agg32(const float* __restrict__ bias,
                                               float* __restrict__ outp) {
    int t = blockIdx.x * blockDim.x + threadIdx.x;
    int n = t >> 5, lane = t & 31;
    if (n >= NN) return;
    const unsigned full = 0xffffffffu;
    int start = g_rowptr[n], end = g_rowptr[n + 1];

    float adst = g_adst[n];
    float acc = 0.f, dacc = 0.f;

    for (int base = start; base < end; base += 32) {
        int cnt = min(32, end - base);
        int myc = (lane < cnt) ? g_col[base + lane] : 0;
        for (int j = 0; j < cnt; j++) {
            int s = __shfl_sync(full, myc, j);
            float asv = g_asrc[s];  // uniform broadcast
            float al = adst + asv;
            al = al > 0.f ? al : 0.2f * al;
            float ex = __expf(al);
            acc += g_h[s * 32 + lane] * ex;
            dacc += ex;
        }
    }
    outp[n * 32 + lane] = acc / dacc + bias[lane];
}

// ---------------- launch ----------------
extern "C" void kernel_launch(void* const* d_in, const int* in_sizes, int n_in,
                              void* d_out, int out_size) {
    const float* x    = (const float*)d_in[0];
    const void*  ei   = d_in[1];
    const float* W1   = (const float*)d_in[2];
    const float* att1 = (const float*)d_in[3];
    const float* b1   = (const float*)d_in[4];
    const float* W2   = (const float*)d_in[5];
    const float* att2 = (const float*)d_in[6];
    const float* b2   = (const float*)d_in[7];
    const float* W3   = (const float*)d_in[8];
    const float* att3 = (const float*)d_in[9];
    const float* b3   = (const float*)d_in[10];
    float* out = (float*)d_out;

    const int TB = 256;
    const int warpGrid = (NN * 32 + TB - 1) / TB;  // one warp per node

    // CSR build (dst is layer-invariant; masked self-loop edges dropped)
    k_detect<<<1, 1>>>(ei);
    k_convert<<<(EE + TB - 1) / TB, TB>>>(ei);
    k_initdeg<<<(NN + TB - 1) / TB, TB>>>();
    k_hist<<<(EE + TB - 1) / TB, TB>>>();
    int nb = (NN + 1023) / 1024;  // 98
    k_scan1<<<nb, 1024>>>();
    k_scan2<<<1, 128>>>(nb);
    k_scan3<<<(NN + TB - 1) / TB, TB>>>();
    k_scatter<<<(EE + NN + TB - 1) / TB, TB>>>();

    // Layer 1: K=128 -> 64, 8 heads
    k_gemm<128, 64, 64, 16><<<(NN + 63) / 64, TB>>>(x, W1, 0);
    k_att8<<<warpGrid, TB>>>(att1);
    k_agg8<<<warpGrid, TB>>>(b1, 1);

    // Layer 2: K=64 -> 64, 8 heads
    k_gemm<64, 64, 64, 16><<<(NN + 63) / 64, TB>>>(nullptr, W2, 1);
    k_att8<<<warpGrid, TB>>>(att2);
    k_agg8<<<warpGrid, TB>>>(b2, 1);

    // Layer 3: K=64 -> 32, 1 head
    k_gemm<64, 32, 128, 8><<<(NN + 127) / 128, TB>>>(nullptr, W3, 1);
    k_att32<<<warpGrid, TB>>>(att3);
    k_agg32<<<warpGrid, TB>>>(b3, out);
}